// round 1
// baseline (speedup 1.0000x reference)
#include <cuda_runtime.h>
#include <cuda_bf16.h>
#include <cstdint>

#define N_NODES 100000
#define DDIM 64
#define HDIM 128
#define N_EDGES 1600000

// Scratch: aggregation buffer (device global — no allocation allowed)
__device__ float g_agg[N_NODES * DDIM];
__device__ int g_idx_is64;

// ---------------------------------------------------------------------------
// Detect whether edge_index is int64 or int32 (JAX x64 ambiguity).
// If genuinely int64 with values < 2^32, all high words are 0.
// If int32 data misread as int64, high words are the odd-position indices,
// which are ~never all zero across 16 samples.
// ---------------------------------------------------------------------------
__global__ void detect_idx_kernel(const unsigned long long* __restrict__ ei) {
    if (threadIdx.x == 0 && blockIdx.x == 0) {
        unsigned long long hi = 0;
        #pragma unroll
        for (int i = 0; i < 16; i++) hi |= (ei[i] >> 32);
        g_idx_is64 = (hi == 0ull) ? 1 : 0;
    }
}

// ---------------------------------------------------------------------------
// agg = (1 + eps) * x   (eps = 0)
// ---------------------------------------------------------------------------
__global__ void init_agg_kernel(const float* __restrict__ x) {
    int i = blockIdx.x * blockDim.x + threadIdx.x;
    if (i < N_NODES * DDIM / 4) {
        ((float4*)g_agg)[i] = ((const float4*)x)[i];
    }
}

// ---------------------------------------------------------------------------
// Scatter: for each edge (s, d): agg[d, :] += x[s, :]
// 16 threads per edge, each doing one float4 vector reduction (red.v4.f32).
// ---------------------------------------------------------------------------
__global__ __launch_bounds__(256) void scatter_kernel(
    const float* __restrict__ x,
    const void* __restrict__ edge_index)
{
    long long t = (long long)blockIdx.x * blockDim.x + threadIdx.x;
    if (t >= (long long)N_EDGES * 16) return;
    int e = (int)(t >> 4);
    int c = ((int)t & 15) << 2;

    int s, d;
    if (g_idx_is64) {
        const long long* ei = (const long long*)edge_index;
        s = (int)ei[e];
        d = (int)ei[N_EDGES + e];
    } else {
        const int* ei = (const int*)edge_index;
        s = ei[e];
        d = ei[N_EDGES + e];
    }

    float4 v = *(const float4*)(x + (size_t)s * DDIM + c);
    float* p = g_agg + (size_t)d * DDIM + c;
    asm volatile("red.global.add.v4.f32 [%0], {%1,%2,%3,%4};"
                 :: "l"(p), "f"(v.x), "f"(v.y), "f"(v.z), "f"(v.w)
                 : "memory");
}

// ---------------------------------------------------------------------------
// MLP: out = relu(agg @ W1 + b1) @ W2 + b2
// Block = 128 threads. W1 (64x128) and W2 (128x64) staged in dynamic shared.
// One node per iteration: thread j computes h[j]; then thread j computes a
// half-K partial of y[j&63] and pairs combine through shared memory.
// ---------------------------------------------------------------------------
__global__ __launch_bounds__(128) void mlp_kernel(
    const float* __restrict__ W1, const float* __restrict__ b1,
    const float* __restrict__ W2, const float* __restrict__ b2,
    float* __restrict__ out)
{
    extern __shared__ float sm[];
    float* sW1 = sm;                 // 64*128
    float* sW2 = sm + DDIM * HDIM;   // 128*64
    float* sb1 = sW2 + HDIM * DDIM;  // 128
    float* sb2 = sb1 + HDIM;         // 64
    float* sx  = sb2 + DDIM;         // 64
    float* sh  = sx + DDIM;          // 128
    float* sp  = sh + HDIM;          // 128 partials

    int tid = threadIdx.x;

    for (int i = tid; i < DDIM * HDIM; i += 128) sW1[i] = W1[i];
    for (int i = tid; i < HDIM * DDIM; i += 128) sW2[i] = W2[i];
    if (tid < HDIM) sb1[tid] = b1[tid];
    if (tid < DDIM) sb2[tid] = b2[tid];
    __syncthreads();

    int dcol = tid & 63;
    int half = tid >> 6;

    for (int n = blockIdx.x; n < N_NODES; n += gridDim.x) {
        // load node row (64 floats) with 16 float4 loads
        if (tid < 16) ((float4*)sx)[tid] = ((const float4*)(g_agg + (size_t)n * DDIM))[tid];
        __syncthreads();

        // h[j] = relu(b1[j] + sum_d sx[d] * W1[d][j])
        float acc = sb1[tid];
        #pragma unroll
        for (int d = 0; d < DDIM; d++)
            acc = fmaf(sx[d], sW1[d * HDIM + tid], acc);
        sh[tid] = fmaxf(acc, 0.0f);
        __syncthreads();

        // y[dcol] partial over K-half
        float acc2 = 0.0f;
        int kbase = half * 64;
        #pragma unroll
        for (int k = 0; k < 64; k++) {
            int kk = kbase + k;
            acc2 = fmaf(sh[kk], sW2[kk * DDIM + dcol], acc2);
        }
        sp[tid] = acc2;
        __syncthreads();

        if (tid < DDIM)
            out[(size_t)n * DDIM + tid] = sp[tid] + sp[tid + 64] + sb2[tid];
        // next iteration's first __syncthreads() (after sx load) protects sp/sh reuse
    }
}

// ---------------------------------------------------------------------------
extern "C" void kernel_launch(void* const* d_in, const int* in_sizes, int n_in,
                              void* d_out, int out_size)
{
    const float* x   = (const float*)d_in[0];
    const void*  ei  = d_in[1];
    const float* W1  = (const float*)d_in[2];
    const float* b1  = (const float*)d_in[3];
    const float* W2  = (const float*)d_in[4];
    const float* b2  = (const float*)d_in[5];
    float* out = (float*)d_out;

    // MLP shared size: W1 + W2 + b1 + b2 + x + h + partials
    int smem = (DDIM * HDIM + HDIM * DDIM + HDIM + DDIM + DDIM + HDIM + HDIM) * sizeof(float);
    cudaFuncSetAttribute(mlp_kernel, cudaFuncAttributeMaxDynamicSharedMemorySize, smem);

    detect_idx_kernel<<<1, 32>>>((const unsigned long long*)ei);

    int initThreads = N_NODES * DDIM / 4;
    init_agg_kernel<<<(initThreads + 255) / 256, 256>>>(x);

    long long scatterThreads = (long long)N_EDGES * 16;
    int scatterBlocks = (int)((scatterThreads + 255) / 256);
    scatter_kernel<<<scatterBlocks, 256>>>(x, ei);

    mlp_kernel<<<888, 128, smem>>>(W1, b1, W2, b2, out);
}

// round 2
// speedup vs baseline: 1.5476x; 1.5476x over previous
#include <cuda_runtime.h>
#include <cuda_bf16.h>
#include <cstdint>

#define N_NODES 100000
#define DDIM 64
#define HDIM 128
#define N_EDGES 1600000

__device__ float g_agg[N_NODES * DDIM];
__device__ int g_idx_is64;

// ---------------------------------------------------------------------------
// Detect int64 vs int32 edge_index (JAX x64 ambiguity).
// ---------------------------------------------------------------------------
__global__ void detect_idx_kernel(const unsigned long long* __restrict__ ei) {
    if (threadIdx.x == 0 && blockIdx.x == 0) {
        unsigned long long hi = 0;
        #pragma unroll
        for (int i = 0; i < 16; i++) hi |= (ei[i] >> 32);
        g_idx_is64 = (hi == 0ull) ? 1 : 0;
    }
}

// ---------------------------------------------------------------------------
// agg = (1 + eps) * x   (eps = 0)
// ---------------------------------------------------------------------------
__global__ void init_agg_kernel(const float* __restrict__ x) {
    int i = blockIdx.x * blockDim.x + threadIdx.x;
    if (i < N_NODES * DDIM / 4) {
        ((float4*)g_agg)[i] = ((const float4*)x)[i];
    }
}

// ---------------------------------------------------------------------------
// Scatter: for each edge (s, d): agg[d, :] += x[s, :] via red.global.add.v4
// ---------------------------------------------------------------------------
__global__ __launch_bounds__(256) void scatter_kernel(
    const float* __restrict__ x,
    const void* __restrict__ edge_index)
{
    long long t = (long long)blockIdx.x * blockDim.x + threadIdx.x;
    if (t >= (long long)N_EDGES * 16) return;
    int e = (int)(t >> 4);
    int c = ((int)t & 15) << 2;

    int s, d;
    if (g_idx_is64) {
        const long long* ei = (const long long*)edge_index;
        s = (int)ei[e];
        d = (int)ei[N_EDGES + e];
    } else {
        const int* ei = (const int*)edge_index;
        s = ei[e];
        d = ei[N_EDGES + e];
    }

    float4 v = *(const float4*)(x + (size_t)s * DDIM + c);
    float* p = g_agg + (size_t)d * DDIM + c;
    asm volatile("red.global.add.v4.f32 [%0], {%1,%2,%3,%4};"
                 :: "l"(p), "f"(v.x), "f"(v.y), "f"(v.z), "f"(v.w)
                 : "memory");
}

// ---------------------------------------------------------------------------
// MLP as a register-blocked tiled GEMM chain.
// Tile = 64 nodes. Weights staged in shared ONCE per persistent block.
// Phase 1: H[64x128] = relu(X @ W1 + b1), thread micro-tile 4x8.
// Phase 2: Y[64x64]  = H @ W2 + b2,       thread micro-tile 2x8.
// smem = W1(32K) + W2(32K) + X(16K) + H(32K) = 112KB -> 2 blocks/SM.
// ---------------------------------------------------------------------------
__global__ __launch_bounds__(256, 2) void mlp_kernel(
    const float* __restrict__ W1, const float* __restrict__ b1,
    const float* __restrict__ W2, const float* __restrict__ b2,
    float* __restrict__ out)
{
    extern __shared__ float sm[];
    float* sW1 = sm;              // [64][128]
    float* sW2 = sW1 + DDIM * HDIM; // [128][64]
    float* sX  = sW2 + HDIM * DDIM; // [64][64]
    float* sH  = sX + 64 * DDIM;    // [64][128]

    int tid = threadIdx.x;

    for (int i = tid; i < DDIM * HDIM; i += 256) sW1[i] = W1[i];
    for (int i = tid; i < HDIM * DDIM; i += 256) sW2[i] = W2[i];

    // phase-1 mapping: 16 col-threads x 16 row-threads, micro 4x8
    int tx1 = tid & 15, ty1 = tid >> 4;
    int r1 = ty1 * 4, c1 = tx1 * 8;
    // phase-2 mapping: 8 col-threads x 32 row-threads, micro 2x8
    int tx2 = tid & 7, ty2 = tid >> 3;
    int r2 = ty2 * 2, c2 = tx2 * 8;

    float b1v[8], b2v[8];
    #pragma unroll
    for (int j = 0; j < 8; j++) b1v[j] = b1[c1 + j];
    #pragma unroll
    for (int j = 0; j < 8; j++) b2v[j] = b2[c2 + j];
    __syncthreads();

    const int ntiles = (N_NODES + 63) / 64;
    for (int tile = blockIdx.x; tile < ntiles; tile += gridDim.x) {
        int base = tile * 64;

        // load X tile: 64x64 floats = 1024 float4, 4 per thread
        #pragma unroll
        for (int t = 0; t < 4; t++) {
            int idx = tid + t * 256;
            int row = idx >> 4, kq = idx & 15;
            float4 v = make_float4(0.f, 0.f, 0.f, 0.f);
            if (base + row < N_NODES)
                v = *(const float4*)(g_agg + (size_t)(base + row) * DDIM + kq * 4);
            *(float4*)(sX + row * DDIM + kq * 4) = v;
        }
        __syncthreads();

        // ---- phase 1: H = relu(X @ W1 + b1) ----
        float acc[4][8];
        #pragma unroll
        for (int i = 0; i < 4; i++)
            #pragma unroll
            for (int j = 0; j < 8; j++) acc[i][j] = b1v[j];

        #pragma unroll 8
        for (int k = 0; k < DDIM; k++) {
            float a0 = sX[(r1 + 0) * DDIM + k];
            float a1 = sX[(r1 + 1) * DDIM + k];
            float a2 = sX[(r1 + 2) * DDIM + k];
            float a3 = sX[(r1 + 3) * DDIM + k];
            float4 blo = *(float4*)(sW1 + k * HDIM + c1);
            float4 bhi = *(float4*)(sW1 + k * HDIM + c1 + 4);
            float bb0 = blo.x, bb1 = blo.y, bb2 = blo.z, bb3 = blo.w;
            float bb4 = bhi.x, bb5 = bhi.y, bb6 = bhi.z, bb7 = bhi.w;
            acc[0][0] = fmaf(a0, bb0, acc[0][0]); acc[0][1] = fmaf(a0, bb1, acc[0][1]);
            acc[0][2] = fmaf(a0, bb2, acc[0][2]); acc[0][3] = fmaf(a0, bb3, acc[0][3]);
            acc[0][4] = fmaf(a0, bb4, acc[0][4]); acc[0][5] = fmaf(a0, bb5, acc[0][5]);
            acc[0][6] = fmaf(a0, bb6, acc[0][6]); acc[0][7] = fmaf(a0, bb7, acc[0][7]);
            acc[1][0] = fmaf(a1, bb0, acc[1][0]); acc[1][1] = fmaf(a1, bb1, acc[1][1]);
            acc[1][2] = fmaf(a1, bb2, acc[1][2]); acc[1][3] = fmaf(a1, bb3, acc[1][3]);
            acc[1][4] = fmaf(a1, bb4, acc[1][4]); acc[1][5] = fmaf(a1, bb5, acc[1][5]);
            acc[1][6] = fmaf(a1, bb6, acc[1][6]); acc[1][7] = fmaf(a1, bb7, acc[1][7]);
            acc[2][0] = fmaf(a2, bb0, acc[2][0]); acc[2][1] = fmaf(a2, bb1, acc[2][1]);
            acc[2][2] = fmaf(a2, bb2, acc[2][2]); acc[2][3] = fmaf(a2, bb3, acc[2][3]);
            acc[2][4] = fmaf(a2, bb4, acc[2][4]); acc[2][5] = fmaf(a2, bb5, acc[2][5]);
            acc[2][6] = fmaf(a2, bb6, acc[2][6]); acc[2][7] = fmaf(a2, bb7, acc[2][7]);
            acc[3][0] = fmaf(a3, bb0, acc[3][0]); acc[3][1] = fmaf(a3, bb1, acc[3][1]);
            acc[3][2] = fmaf(a3, bb2, acc[3][2]); acc[3][3] = fmaf(a3, bb3, acc[3][3]);
            acc[3][4] = fmaf(a3, bb4, acc[3][4]); acc[3][5] = fmaf(a3, bb5, acc[3][5]);
            acc[3][6] = fmaf(a3, bb6, acc[3][6]); acc[3][7] = fmaf(a3, bb7, acc[3][7]);
        }

        // relu + store H (float4 x2 per row)
        #pragma unroll
        for (int i = 0; i < 4; i++) {
            float4 lo, hi;
            lo.x = fmaxf(acc[i][0], 0.f); lo.y = fmaxf(acc[i][1], 0.f);
            lo.z = fmaxf(acc[i][2], 0.f); lo.w = fmaxf(acc[i][3], 0.f);
            hi.x = fmaxf(acc[i][4], 0.f); hi.y = fmaxf(acc[i][5], 0.f);
            hi.z = fmaxf(acc[i][6], 0.f); hi.w = fmaxf(acc[i][7], 0.f);
            *(float4*)(sH + (r1 + i) * HDIM + c1)     = lo;
            *(float4*)(sH + (r1 + i) * HDIM + c1 + 4) = hi;
        }
        __syncthreads();

        // ---- phase 2: Y = H @ W2 + b2 ----
        float acc2[2][8];
        #pragma unroll
        for (int i = 0; i < 2; i++)
            #pragma unroll
            for (int j = 0; j < 8; j++) acc2[i][j] = 0.f;

        #pragma unroll 8
        for (int k = 0; k < HDIM; k++) {
            float a0 = sH[(r2 + 0) * HDIM + k];
            float a1 = sH[(r2 + 1) * HDIM + k];
            float4 blo = *(float4*)(sW2 + k * DDIM + c2);
            float4 bhi = *(float4*)(sW2 + k * DDIM + c2 + 4);
            acc2[0][0] = fmaf(a0, blo.x, acc2[0][0]); acc2[0][1] = fmaf(a0, blo.y, acc2[0][1]);
            acc2[0][2] = fmaf(a0, blo.z, acc2[0][2]); acc2[0][3] = fmaf(a0, blo.w, acc2[0][3]);
            acc2[0][4] = fmaf(a0, bhi.x, acc2[0][4]); acc2[0][5] = fmaf(a0, bhi.y, acc2[0][5]);
            acc2[0][6] = fmaf(a0, bhi.z, acc2[0][6]); acc2[0][7] = fmaf(a0, bhi.w, acc2[0][7]);
            acc2[1][0] = fmaf(a1, blo.x, acc2[1][0]); acc2[1][1] = fmaf(a1, blo.y, acc2[1][1]);
            acc2[1][2] = fmaf(a1, blo.z, acc2[1][2]); acc2[1][3] = fmaf(a1, blo.w, acc2[1][3]);
            acc2[1][4] = fmaf(a1, bhi.x, acc2[1][4]); acc2[1][5] = fmaf(a1, bhi.y, acc2[1][5]);
            acc2[1][6] = fmaf(a1, bhi.z, acc2[1][6]); acc2[1][7] = fmaf(a1, bhi.w, acc2[1][7]);
        }

        #pragma unroll
        for (int i = 0; i < 2; i++) {
            int row = base + r2 + i;
            if (row < N_NODES) {
                float4 lo, hi;
                lo.x = acc2[i][0] + b2v[0]; lo.y = acc2[i][1] + b2v[1];
                lo.z = acc2[i][2] + b2v[2]; lo.w = acc2[i][3] + b2v[3];
                hi.x = acc2[i][4] + b2v[4]; hi.y = acc2[i][5] + b2v[5];
                hi.z = acc2[i][6] + b2v[6]; hi.w = acc2[i][7] + b2v[7];
                *(float4*)(out + (size_t)row * DDIM + c2)     = lo;
                *(float4*)(out + (size_t)row * DDIM + c2 + 4) = hi;
            }
        }
        __syncthreads();   // protect sX / sH before next tile
    }
}

// ---------------------------------------------------------------------------
extern "C" void kernel_launch(void* const* d_in, const int* in_sizes, int n_in,
                              void* d_out, int out_size)
{
    const float* x   = (const float*)d_in[0];
    const void*  ei  = d_in[1];
    const float* W1  = (const float*)d_in[2];
    const float* b1  = (const float*)d_in[3];
    const float* W2  = (const float*)d_in[4];
    const float* b2  = (const float*)d_in[5];
    float* out = (float*)d_out;

    int smem = (DDIM * HDIM + HDIM * DDIM + 64 * DDIM + 64 * HDIM) * sizeof(float); // 112KB
    cudaFuncSetAttribute(mlp_kernel, cudaFuncAttributeMaxDynamicSharedMemorySize, smem);

    detect_idx_kernel<<<1, 32>>>((const unsigned long long*)ei);

    int initThreads = N_NODES * DDIM / 4;
    init_agg_kernel<<<(initThreads + 255) / 256, 256>>>(x);

    long long scatterThreads = (long long)N_EDGES * 16;
    int scatterBlocks = (int)((scatterThreads + 255) / 256);
    scatter_kernel<<<scatterBlocks, 256>>>(x, ei);

    mlp_kernel<<<296, 256, smem>>>(W1, b1, W2, b2, out);
}

// round 4
// speedup vs baseline: 2.1132x; 1.3654x over previous
#include <cuda_runtime.h>
#include <cuda_bf16.h>
#include <cstdint>

#define N_NODES 100000
#define DDIM 64
#define HDIM 128
#define N_EDGES 1600000

__device__ float g_agg[N_NODES * DDIM];
__device__ int g_idx_is64;

// ---------------------------------------------------------------------------
// Detect int64 vs int32 edge_index (JAX x64 ambiguity).
// ---------------------------------------------------------------------------
__global__ void detect_idx_kernel(const unsigned long long* __restrict__ ei) {
    if (threadIdx.x == 0 && blockIdx.x == 0) {
        unsigned long long hi = 0;
        #pragma unroll
        for (int i = 0; i < 16; i++) hi |= (ei[i] >> 32);
        g_idx_is64 = (hi == 0ull) ? 1 : 0;
    }
}

// ---------------------------------------------------------------------------
// agg = (1 + eps) * x   (eps = 0)
// ---------------------------------------------------------------------------
__global__ void init_agg_kernel(const float* __restrict__ x) {
    int i = blockIdx.x * blockDim.x + threadIdx.x;
    if (i < N_NODES * DDIM / 4) {
        ((float4*)g_agg)[i] = ((const float4*)x)[i];
    }
}

// ---------------------------------------------------------------------------
// Scatter: for each edge (s, d): agg[d, :] += x[s, :] via red.global.add.v4
// ---------------------------------------------------------------------------
__global__ __launch_bounds__(256) void scatter_kernel(
    const float* __restrict__ x,
    const void* __restrict__ edge_index)
{
    long long t = (long long)blockIdx.x * blockDim.x + threadIdx.x;
    if (t >= (long long)N_EDGES * 16) return;
    int e = (int)(t >> 4);
    int c = ((int)t & 15) << 2;

    int s, d;
    if (g_idx_is64) {
        const long long* ei = (const long long*)edge_index;
        s = (int)ei[e];
        d = (int)ei[N_EDGES + e];
    } else {
        const int* ei = (const int*)edge_index;
        s = ei[e];
        d = ei[N_EDGES + e];
    }

    float4 v = *(const float4*)(x + (size_t)s * DDIM + c);
    float* p = g_agg + (size_t)d * DDIM + c;
    asm volatile("red.global.add.v4.f32 [%0], {%1,%2,%3,%4};"
                 :: "l"(p), "f"(v.x), "f"(v.y), "f"(v.z), "f"(v.w)
                 : "memory");
}

// ---------------------------------------------------------------------------
// MLP v3: 128 threads/block, 64-node tile, 8x8 micro-tile phase 1 (broadcast
// A-loads), 8x4 phase 2. Weights resident in smem per persistent block.
// smem = W1(32K) + W2(32K) + X(16K) + H(32K) = 112KB -> 2 blocks/SM.
// ---------------------------------------------------------------------------
__global__ __launch_bounds__(128, 2) void mlp_kernel(
    const float* __restrict__ W1, const float* __restrict__ b1,
    const float* __restrict__ W2, const float* __restrict__ b2,
    float* __restrict__ out)
{
    extern __shared__ float sm[];
    float* sW1 = sm;                 // [64][128]
    float* sW2 = sW1 + DDIM * HDIM;  // [128][64]
    float* sX  = sW2 + HDIM * DDIM;  // [64][64]
    float* sH  = sX + 64 * DDIM;     // [64][128]

    int tid = threadIdx.x;
    int tx = tid & 15;     // 16 column-groups
    int ty = tid >> 4;     // 8 row-groups
    int r  = ty * 8;       // rows r..r+7
    int c1 = tx * 8;       // phase-1 cols (128 / 8 = 16)
    int c2 = tx * 4;       // phase-2 cols (64 / 4 = 16)

    for (int i = tid; i < DDIM * HDIM; i += 128) sW1[i] = W1[i];
    for (int i = tid; i < HDIM * DDIM; i += 128) sW2[i] = W2[i];

    float b1v[8], b2v[4];
    #pragma unroll
    for (int j = 0; j < 8; j++) b1v[j] = b1[c1 + j];
    #pragma unroll
    for (int j = 0; j < 4; j++) b2v[j] = b2[c2 + j];
    __syncthreads();

    const int ntiles = (N_NODES + 63) / 64;
    for (int tile = blockIdx.x; tile < ntiles; tile += gridDim.x) {
        int base = tile * 64;

        // load X tile: 64x64 = 1024 float4, 8 per thread
        #pragma unroll
        for (int t = 0; t < 8; t++) {
            int idx = tid + t * 128;
            int row = idx >> 4, kq = idx & 15;
            float4 v = make_float4(0.f, 0.f, 0.f, 0.f);
            if (base + row < N_NODES)
                v = *(const float4*)(g_agg + (size_t)(base + row) * DDIM + kq * 4);
            *(float4*)(sX + row * DDIM + kq * 4) = v;
        }
        __syncthreads();

        // ---- phase 1: H = relu(X @ W1 + b1), 8x8 per thread ----
        float acc[8][8];
        #pragma unroll
        for (int i = 0; i < 8; i++)
            #pragma unroll
            for (int j = 0; j < 8; j++) acc[i][j] = b1v[j];

        #pragma unroll 4
        for (int k = 0; k < DDIM; k++) {
            float a[8];
            #pragma unroll
            for (int i = 0; i < 8; i++) a[i] = sX[(r + i) * DDIM + k];
            float4 blo = *(float4*)(sW1 + k * HDIM + c1);
            float4 bhi = *(float4*)(sW1 + k * HDIM + c1 + 4);
            float bb[8] = {blo.x, blo.y, blo.z, blo.w, bhi.x, bhi.y, bhi.z, bhi.w};
            #pragma unroll
            for (int i = 0; i < 8; i++)
                #pragma unroll
                for (int j = 0; j < 8; j++)
                    acc[i][j] = fmaf(a[i], bb[j], acc[i][j]);
        }

        // relu + store H rows
        #pragma unroll
        for (int i = 0; i < 8; i++) {
            float4 lo, hi;
            lo.x = fmaxf(acc[i][0], 0.f); lo.y = fmaxf(acc[i][1], 0.f);
            lo.z = fmaxf(acc[i][2], 0.f); lo.w = fmaxf(acc[i][3], 0.f);
            hi.x = fmaxf(acc[i][4], 0.f); hi.y = fmaxf(acc[i][5], 0.f);
            hi.z = fmaxf(acc[i][6], 0.f); hi.w = fmaxf(acc[i][7], 0.f);
            *(float4*)(sH + (r + i) * HDIM + c1)     = lo;
            *(float4*)(sH + (r + i) * HDIM + c1 + 4) = hi;
        }
        __syncthreads();

        // ---- phase 2: Y = H @ W2 + b2, 8x4 per thread ----
        float acc2[8][4];
        #pragma unroll
        for (int i = 0; i < 8; i++)
            #pragma unroll
            for (int j = 0; j < 4; j++) acc2[i][j] = 0.f;

        #pragma unroll 4
        for (int k = 0; k < HDIM; k++) {
            float a[8];
            #pragma unroll
            for (int i = 0; i < 8; i++) a[i] = sH[(r + i) * HDIM + k];
            float4 b = *(float4*)(sW2 + k * DDIM + c2);
            float bb[4] = {b.x, b.y, b.z, b.w};
            #pragma unroll
            for (int i = 0; i < 8; i++)
                #pragma unroll
                for (int j = 0; j < 4; j++)
                    acc2[i][j] = fmaf(a[i], bb[j], acc2[i][j]);
        }

        #pragma unroll
        for (int i = 0; i < 8; i++) {
            int row = base + r + i;
            if (row < N_NODES) {
                float4 v;
                v.x = acc2[i][0] + b2v[0];
                v.y = acc2[i][1] + b2v[1];
                v.z = acc2[i][2] + b2v[2];
                v.w = acc2[i][3] + b2v[3];
                *(float4*)(out + (size_t)row * DDIM + c2) = v;
            }
        }
        __syncthreads();   // protect sX / sH before next tile
    }
}

// ---------------------------------------------------------------------------
extern "C" void kernel_launch(void* const* d_in, const int* in_sizes, int n_in,
                              void* d_out, int out_size)
{
    const float* x   = (const float*)d_in[0];
    const void*  ei  = d_in[1];
    const float* W1  = (const float*)d_in[2];
    const float* b1  = (const float*)d_in[3];
    const float* W2  = (const float*)d_in[4];
    const float* b2  = (const float*)d_in[5];
    float* out = (float*)d_out;

    int smem = (DDIM * HDIM + HDIM * DDIM + 64 * DDIM + 64 * HDIM) * sizeof(float); // 112KB
    cudaFuncSetAttribute(mlp_kernel, cudaFuncAttributeMaxDynamicSharedMemorySize, smem);

    detect_idx_kernel<<<1, 32>>>((const unsigned long long*)ei);

    int initThreads = N_NODES * DDIM / 4;
    init_agg_kernel<<<(initThreads + 255) / 256, 256>>>(x);

    long long scatterThreads = (long long)N_EDGES * 16;
    int scatterBlocks = (int)((scatterThreads + 255) / 256);
    scatter_kernel<<<scatterBlocks, 256>>>(x, ei);

    mlp_kernel<<<296, 128, smem>>>(W1, b1, W2, b2, out);
}